// round 12
// baseline (speedup 1.0000x reference)
#include <cuda_runtime.h>
#include <cuda_fp16.h>
#include <cstdint>

#define D        64
#define H        64
#define TPB      128
#define NW       4
#define TILE_M   128
#define CTAS_PER_SM 3
#define NMAXROW  100000

#define XSTRH    136             // halfs/row; 272 B stride (conflict-free, 16B aligned)
#define BSTRH    136

// dynamic smem layout (bytes)
#define SM_X      0
#define SM_XW     (32 * XSTRH * 2)                // 8704 B per warp (32 rows)
#define SM_X_SZ   (NW * SM_XW)                    // 34816
#define SM_B      (SM_X + SM_X_SZ)
#define SM_B_SZ   (H * BSTRH * 2)                 // 17408
#define SM_EA     (SM_B + SM_B_SZ)                // float4[32]: (w1c, w1c, b1, b1) pairs
#define SM_EB     (SM_EA + 512)                   // float2[32]: W2 pairs
#define SM_B2     (SM_EB + 256)
#define SM_TOTAL  (SM_B2 + 16)                    // ~53 KB

__device__ __align__(16) __half  g_hc_h[NMAXROW * D];
__device__ __align__(16) __half  g_hp_h[NMAXROW * D];
__device__ __align__(16) __half  g_Bimg[H * BSTRH];
__device__ __align__(16) float4  g_EA[32];
__device__ __align__(16) float2  g_EB[32];

__global__ void prep_all(const float* __restrict__ hc, const float* __restrict__ hp,
                         const float* __restrict__ W1, const float* __restrict__ b1,
                         const float* __restrict__ W2, int n4c, int n4p) {
    int i = blockIdx.x * blockDim.x + threadIdx.x;
    if (i < n4c) {
        float4 v = ((const float4*)hc)[i];
        ((__half2*)g_hc_h)[2 * i]     = __floats2half2_rn(v.x, v.y);
        ((__half2*)g_hc_h)[2 * i + 1] = __floats2half2_rn(v.z, v.w);
    } else if (i < n4c + n4p) {
        int k = i - n4c;
        float4 v = ((const float4*)hp)[k];
        ((__half2*)g_hp_h)[2 * k]     = __floats2half2_rn(v.x, v.y);
        ((__half2*)g_hp_h)[2 * k + 1] = __floats2half2_rn(v.z, v.w);
    }
    if (i < H * BSTRH) {
        int n = i / BSTRH, k = i % BSTRH;
        g_Bimg[i] = __float2half_rn((k < 2 * D) ? W1[k * H + n] : 0.0f);
    }
    if (i < 32) {
        int n = 2 * i;
        g_EA[i] = make_float4(W1[2 * D * H + n], W1[2 * D * H + n + 1], b1[n], b1[n + 1]);
        g_EB[i] = make_float2(W2[n], W2[n + 1]);
    }
}

__device__ __forceinline__ uint32_t smem_u32(const void* p) {
    uint32_t a;
    asm("{ .reg .u64 t; cvta.to.shared.u64 t, %1; cvt.u32.u64 %0, t; }" : "=r"(a) : "l"(p));
    return a;
}
__device__ __forceinline__ void cp16(uint32_t saddr, const void* gaddr) {
    asm volatile("cp.async.cg.shared.global [%0], [%1], 16;" :: "r"(saddr), "l"(gaddr));
}
__device__ __forceinline__ void ldsm_x4(uint32_t& r0, uint32_t& r1, uint32_t& r2, uint32_t& r3,
                                        uint32_t addr) {
    asm volatile("ldmatrix.sync.aligned.m8n8.x4.shared.b16 {%0,%1,%2,%3}, [%4];"
                 : "=r"(r0), "=r"(r1), "=r"(r2), "=r"(r3) : "r"(addr));
}
__device__ __forceinline__ void mma_f16(float c[4],
                                        uint32_t a0, uint32_t a1, uint32_t a2, uint32_t a3,
                                        uint32_t b0, uint32_t b1) {
    asm volatile(
        "mma.sync.aligned.m16n8k16.row.col.f32.f16.f16.f32 "
        "{%0,%1,%2,%3}, {%4,%5,%6,%7}, {%8,%9}, {%0,%1,%2,%3};"
        : "+f"(c[0]), "+f"(c[1]), "+f"(c[2]), "+f"(c[3])
        : "r"(a0), "r"(a1), "r"(a2), "r"(a3), "r"(b0), "r"(b1));
}
__device__ __forceinline__ __half2 u2h(uint32_t u) { return *(__half2*)&u; }

__global__ __launch_bounds__(TPB, CTAS_PER_SM)
void edge_mlp_f16_kernel(const int*   __restrict__ src,
                         const int*   __restrict__ dst,
                         const float* __restrict__ b2,
                         float*       __restrict__ out,
                         int E, int ntiles)
{
    extern __shared__ char smem[];
    const uint32_t smem_base = smem_u32(smem);
    float4* sEA = (float4*)(smem + SM_EA);
    float2* sEB = (float2*)(smem + SM_EB);
    float*  sB2 = (float*)(smem + SM_B2);

    const int tid   = threadIdx.x;
    const int wid   = tid >> 5;
    const int lane  = tid & 31;
    const int ngrid = gridDim.x;

    const uint32_t xw = smem_base + SM_X + (uint32_t)wid * SM_XW;

    // gather role constants
    const int el2   = lane >> 4;
    const int part  = (lane >> 3) & 1;
    const int chunk = lane & 7;

    // ---- stage-0 indices ----
    int tile0 = blockIdx.x;
    int ec = tile0 * TILE_M + wid * 32 + lane; if (ec >= E) ec = E - 1;
    int sv = src[ec], tv = dst[ec];

    // ---- B / epilogue-table staging (once) ----
    {
        const char* gB = (const char*)g_Bimg;
        uint32_t dB = smem_base + SM_B;
        #pragma unroll
        for (int i = 0; i < 9; ++i) {
            int c = i * TPB + tid;
            if (c < SM_B_SZ / 16) cp16(dB + (uint32_t)c * 16u, gB + c * 16);
        }
    }
    if (tid < 32) { sEA[tid] = g_EA[tid]; sEB[tid] = g_EB[tid]; }
    if (tid == 0) sB2[0] = b2[0];

    // ---- gather stage 0 ----
    #pragma unroll 8
    for (int i = 0; i < 16; ++i) {
        int ew = 2 * i + el2;
        int si = __shfl_sync(0xffffffffu, sv, ew);
        int ti = __shfl_sync(0xffffffffu, tv, ew);
        const __half* g = part ? g_hp_h + (size_t)ti * D + chunk * 8
                               : g_hc_h + (size_t)si * D + chunk * 8;
        cp16(xw + (uint32_t)ew * (XSTRH * 2u) + (uint32_t)(part * 128 + chunk * 16), g);
    }
    asm volatile("cp.async.commit_group;" ::: "memory");

    // ---- prefetch stage-1 indices ----
    {
        long long bb = (long long)(tile0 + ngrid) * TILE_M + wid * 32 + lane;
        int ecl = (bb < E) ? (int)bb : (E - 1);
        sv = src[ecl]; tv = dst[ecl];
    }

    asm volatile("cp.async.wait_group 0;" ::: "memory");
    __syncthreads();                 // B/tables visible; only CTA-wide barrier

    // ---- ldmatrix addresses ----
    const int j = lane >> 3;
    const int r = lane & 7;
    const uint32_t aA0 = xw + (uint32_t)(((j & 1) * 8 + r) * (XSTRH * 2)) + (uint32_t)(j >> 1) * 16u;
    const uint32_t aA1 = aA0 + 16u * (XSTRH * 2u);
    uint32_t aB[4];
    #pragma unroll
    for (int p = 0; p < 4; ++p)
        aB[p] = smem_base + SM_B
              + (uint32_t)((p * 16 + r + (j >> 1) * 8) * (BSTRH * 2))
              + (uint32_t)(j & 1) * 16u;

    const int qrow  = lane >> 2;
    const int qlane = lane & 3;
    const float bias2v = sB2[0];

    // =================== stage loop ===================
    for (int tile = tile0; tile < ntiles; tile += ngrid) {
        float acc[2][8][4];
        #pragma unroll
        for (int mt = 0; mt < 2; ++mt)
            #pragma unroll
            for (int nt = 0; nt < 8; ++nt)
                #pragma unroll
                for (int c = 0; c < 4; ++c) acc[mt][nt][c] = 0.f;

        // cosine accumulators: [mt][row-half] (rows qrow / qrow+8 of each m-tile)
        __half2 cnh[2][2], cnt[2][2], cdp[2][2];
        #pragma unroll
        for (int mt = 0; mt < 2; ++mt)
            #pragma unroll
            for (int h = 0; h < 2; ++h) {
                cnh[mt][h] = __float2half2_rn(0.f);
                cnt[mt][h] = __float2half2_rn(0.f);
                cdp[mt][h] = __float2half2_rn(0.f);
            }

        // ---- fused k-loop: pairs (ks, ks+4) = (head cols, tail cols) ----
        #pragma unroll
        for (int ksp = 0; ksp < 4; ++ksp) {
            const uint32_t ko  = (uint32_t)ksp * 32u;
            const uint32_t ko2 = ko + 128u;

            uint32_t ah[2][4], at[2][4];
            ldsm_x4(ah[0][0], ah[0][1], ah[0][2], ah[0][3], aA0 + ko);
            ldsm_x4(ah[1][0], ah[1][1], ah[1][2], ah[1][3], aA1 + ko);
            ldsm_x4(at[0][0], at[0][1], at[0][2], at[0][3], aA0 + ko2);
            ldsm_x4(at[1][0], at[1][1], at[1][2], at[1][3], aA1 + ko2);

            // cosine partials from fragments (head: a0/a2=row qrow, a1/a3=row qrow+8)
            #pragma unroll
            for (int mt = 0; mt < 2; ++mt) {
                __half2 h0a = u2h(ah[mt][0]), h0b = u2h(ah[mt][2]);
                __half2 h1a = u2h(ah[mt][1]), h1b = u2h(ah[mt][3]);
                __half2 t0a = u2h(at[mt][0]), t0b = u2h(at[mt][2]);
                __half2 t1a = u2h(at[mt][1]), t1b = u2h(at[mt][3]);
                cnh[mt][0] = __hfma2(h0a, h0a, cnh[mt][0]);
                cnh[mt][0] = __hfma2(h0b, h0b, cnh[mt][0]);
                cnh[mt][1] = __hfma2(h1a, h1a, cnh[mt][1]);
                cnh[mt][1] = __hfma2(h1b, h1b, cnh[mt][1]);
                cnt[mt][0] = __hfma2(t0a, t0a, cnt[mt][0]);
                cnt[mt][0] = __hfma2(t0b, t0b, cnt[mt][0]);
                cnt[mt][1] = __hfma2(t1a, t1a, cnt[mt][1]);
                cnt[mt][1] = __hfma2(t1b, t1b, cnt[mt][1]);
                cdp[mt][0] = __hfma2(h0a, t0a, cdp[mt][0]);
                cdp[mt][0] = __hfma2(h0b, t0b, cdp[mt][0]);
                cdp[mt][1] = __hfma2(h1a, t1a, cdp[mt][1]);
                cdp[mt][1] = __hfma2(h1b, t1b, cdp[mt][1]);
            }

            // B fragments + MMAs: head k-step
            {
                uint32_t bf[8][2];
                #pragma unroll
                for (int p = 0; p < 4; ++p) {
                    uint32_t r0, r1, r2, r3;
                    ldsm_x4(r0, r1, r2, r3, aB[p] + ko);
                    bf[2*p][0] = r0;   bf[2*p][1] = r1;
                    bf[2*p+1][0] = r2; bf[2*p+1][1] = r3;
                }
                #pragma unroll
                for (int nt = 0; nt < 8; ++nt) {
                    mma_f16(acc[0][nt], ah[0][0], ah[0][1], ah[0][2], ah[0][3], bf[nt][0], bf[nt][1]);
                    mma_f16(acc[1][nt], ah[1][0], ah[1][1], ah[1][2], ah[1][3], bf[nt][0], bf[nt][1]);
                }
            }
            // tail k-step
            {
                uint32_t bf[8][2];
                #pragma unroll
                for (int p = 0; p < 4; ++p) {
                    uint32_t r0, r1, r2, r3;
                    ldsm_x4(r0, r1, r2, r3, aB[p] + ko2);
                    bf[2*p][0] = r0;   bf[2*p][1] = r1;
                    bf[2*p+1][0] = r2; bf[2*p+1][1] = r3;
                }
                #pragma unroll
                for (int nt = 0; nt < 8; ++nt) {
                    mma_f16(acc[0][nt], at[0][0], at[0][1], at[0][2], at[0][3], bf[nt][0], bf[nt][1]);
                    mma_f16(acc[1][nt], at[1][0], at[1][1], at[1][2], at[1][3], bf[nt][0], bf[nt][1]);
                }
            }
        }
        __syncwarp();   // all LDSMs done -> X buffer reusable

        // ---- issue gather for next stage ----
        const int tnext = tile + ngrid;
        if (tnext < ntiles) {
            #pragma unroll 8
            for (int i = 0; i < 16; ++i) {
                int ew = 2 * i + el2;
                int si = __shfl_sync(0xffffffffu, sv, ew);
                int ti = __shfl_sync(0xffffffffu, tv, ew);
                const __half* g = part ? g_hp_h + (size_t)ti * D + chunk * 8
                                       : g_hc_h + (size_t)si * D + chunk * 8;
                cp16(xw + (uint32_t)ew * (XSTRH * 2u) + (uint32_t)(part * 128 + chunk * 16), g);
            }
        }
        asm volatile("cp.async.commit_group;" ::: "memory");

        // ---- prefetch indices for stage after next ----
        {
            long long bb = (long long)(tile + 2 * ngrid) * TILE_M + wid * 32 + lane;
            int ecl = (bb >= 0 && bb < E) ? (int)bb : (E - 1);
            sv = src[ecl]; tv = dst[ecl];
        }

        // ---- finalize cosines (quad butterfly -> all lanes have row sums) ----
        float cos4[2][2];
        #pragma unroll
        for (int mt = 0; mt < 2; ++mt)
            #pragma unroll
            for (int h = 0; h < 2; ++h) {
                float2 a = __half22float2(cnh[mt][h]);
                float2 b = __half22float2(cnt[mt][h]);
                float2 c = __half22float2(cdp[mt][h]);
                float nh = a.x + a.y, nt = b.x + b.y, dp = c.x + c.y;
                nh += __shfl_xor_sync(0xffffffffu, nh, 1);
                nh += __shfl_xor_sync(0xffffffffu, nh, 2);
                nt += __shfl_xor_sync(0xffffffffu, nt, 1);
                nt += __shfl_xor_sync(0xffffffffu, nt, 2);
                dp += __shfl_xor_sync(0xffffffffu, dp, 1);
                dp += __shfl_xor_sync(0xffffffffu, dp, 2);
                cos4[mt][h] = dp * rsqrtf(fmaxf(nh * nt, 1e-24f));
            }

        // ---- epilogue: +cos*w1c + b1, relu, dot W2, sigmoid ----
        {
            float4 ea[8]; float2 eb[8];
            #pragma unroll
            for (int nt = 0; nt < 8; ++nt) {
                ea[nt] = sEA[nt * 4 + qlane];
                eb[nt] = sEB[nt * 4 + qlane];
            }
            const int ebase = tile * TILE_M + wid * 32;
            #pragma unroll
            for (int mt = 0; mt < 2; ++mt) {
                #pragma unroll
                for (int rr = 0; rr < 2; ++rr) {
                    const float cR = cos4[mt][rr];
                    float z = 0.f;
                    #pragma unroll
                    for (int nt = 0; nt < 8; ++nt) {
                        float v0 = acc[mt][nt][2*rr]     + fmaf(cR, ea[nt].x, ea[nt].z);
                        float v1 = acc[mt][nt][2*rr + 1] + fmaf(cR, ea[nt].y, ea[nt].w);
                        z = fmaf(fmaxf(v0, 0.f), eb[nt].x, z);
                        z = fmaf(fmaxf(v1, 0.f), eb[nt].y, z);
                    }
                    z += __shfl_xor_sync(0xffffffffu, z, 1);
                    z += __shfl_xor_sync(0xffffffffu, z, 2);
                    if (qlane == 0) {
                        int eo = ebase + mt * 16 + rr * 8 + qrow;
                        if (eo < E) {
                            float zz = z + bias2v;
                            out[eo] = 1.0f / (1.0f + expf(-zz));
                        }
                    }
                }
            }
        }

        asm volatile("cp.async.wait_group 0;" ::: "memory");
        __syncwarp();
    }
}

extern "C" void kernel_launch(void* const* d_in, const int* in_sizes, int n_in,
                              void* d_out, int out_size)
{
    const float* hc  = (const float*)d_in[0];
    const float* hp  = (const float*)d_in[1];
    const int*   src = (const int*)  d_in[2];
    const int*   dst = (const int*)  d_in[3];
    const float* W1  = (const float*)d_in[4];
    const float* b1  = (const float*)d_in[5];
    const float* W2  = (const float*)d_in[6];
    const float* b2  = (const float*)d_in[7];
    float* out = (float*)d_out;

    static int nsm = 0;
    if (!nsm) {
        cudaDeviceGetAttribute(&nsm, cudaDevAttrMultiProcessorCount, 0);
        cudaFuncSetAttribute(edge_mlp_f16_kernel,
                             cudaFuncAttributeMaxDynamicSharedMemorySize, SM_TOTAL);
    }

    int E   = in_sizes[2];
    int n4c = in_sizes[0] / 4;
    int n4p = in_sizes[1] / 4;
    int n4  = n4c + n4p;

    prep_all<<<(n4 + 255) / 256, 256>>>(hc, hp, W1, b1, W2, n4c, n4p);

    int ntiles = (E + TILE_M - 1) / TILE_M;
    int ngrid  = nsm * CTAS_PER_SM;
    if (ngrid > ntiles) ngrid = ntiles;
    edge_mlp_f16_kernel<<<ngrid, TPB, SM_TOTAL>>>(src, dst, b2, out, E, ntiles);
}

// round 13
// speedup vs baseline: 1.0589x; 1.0589x over previous
#include <cuda_runtime.h>
#include <cuda_fp16.h>
#include <cstdint>

#define D        64
#define H        64
#define TPB      128
#define NW       4
#define TILE_M   128
#define CTAS_PER_SM 3
#define NMAXROW  100000

#define XSTRH    136             // halfs/row; 272 B stride (conflict-free, 16B aligned)
#define BSTRH    136

// dynamic smem layout (bytes)
#define SM_X      0
#define SM_XW     (32 * XSTRH * 2)                // 8704 B per warp (32 rows)
#define SM_X_SZ   (NW * SM_XW)                    // 34816
#define SM_B      (SM_X + SM_X_SZ)
#define SM_B_SZ   (H * BSTRH * 2)                 // 17408
#define SM_EA     (SM_B + SM_B_SZ)                // float4[32]: (w1c, w1c, b1, b1) pairs
#define SM_EB     (SM_EA + 512)                   // float2[32]: W2 pairs
#define SM_B2     (SM_EB + 256)
#define SM_TOTAL  (SM_B2 + 16)                    // ~53 KB

__device__ __align__(16) __half  g_hc_h[NMAXROW * D];
__device__ __align__(16) __half  g_hp_h[NMAXROW * D];
__device__ __align__(16) __half  g_Bimg[H * BSTRH];
__device__ __align__(16) float4  g_EA[32];
__device__ __align__(16) float2  g_EB[32];

__global__ void prep_all(const float* __restrict__ hc, const float* __restrict__ hp,
                         const float* __restrict__ W1, const float* __restrict__ b1,
                         const float* __restrict__ W2, int n4c, int n4p) {
    int i = blockIdx.x * blockDim.x + threadIdx.x;
    if (i < n4c) {
        float4 v = ((const float4*)hc)[i];
        ((__half2*)g_hc_h)[2 * i]     = __floats2half2_rn(v.x, v.y);
        ((__half2*)g_hc_h)[2 * i + 1] = __floats2half2_rn(v.z, v.w);
    } else if (i < n4c + n4p) {
        int k = i - n4c;
        float4 v = ((const float4*)hp)[k];
        ((__half2*)g_hp_h)[2 * k]     = __floats2half2_rn(v.x, v.y);
        ((__half2*)g_hp_h)[2 * k + 1] = __floats2half2_rn(v.z, v.w);
    }
    if (i < H * BSTRH) {
        int n = i / BSTRH, k = i % BSTRH;
        g_Bimg[i] = __float2half_rn((k < 2 * D) ? W1[k * H + n] : 0.0f);
    }
    if (i < 32) {
        int n = 2 * i;
        g_EA[i] = make_float4(W1[2 * D * H + n], W1[2 * D * H + n + 1], b1[n], b1[n + 1]);
        g_EB[i] = make_float2(W2[n], W2[n + 1]);
    }
}

__device__ __forceinline__ uint32_t smem_u32(const void* p) {
    uint32_t a;
    asm("{ .reg .u64 t; cvta.to.shared.u64 t, %1; cvt.u32.u64 %0, t; }" : "=r"(a) : "l"(p));
    return a;
}
__device__ __forceinline__ void cp16(uint32_t saddr, const void* gaddr) {
    asm volatile("cp.async.cg.shared.global [%0], [%1], 16;" :: "r"(saddr), "l"(gaddr));
}
__device__ __forceinline__ void ldsm_x4(uint32_t& r0, uint32_t& r1, uint32_t& r2, uint32_t& r3,
                                        uint32_t addr) {
    asm volatile("ldmatrix.sync.aligned.m8n8.x4.shared.b16 {%0,%1,%2,%3}, [%4];"
                 : "=r"(r0), "=r"(r1), "=r"(r2), "=r"(r3) : "r"(addr));
}
__device__ __forceinline__ void mma_f16(float c[4],
                                        uint32_t a0, uint32_t a1, uint32_t a2, uint32_t a3,
                                        uint32_t b0, uint32_t b1) {
    asm volatile(
        "mma.sync.aligned.m16n8k16.row.col.f32.f16.f16.f32 "
        "{%0,%1,%2,%3}, {%4,%5,%6,%7}, {%8,%9}, {%0,%1,%2,%3};"
        : "+f"(c[0]), "+f"(c[1]), "+f"(c[2]), "+f"(c[3])
        : "r"(a0), "r"(a1), "r"(a2), "r"(a3), "r"(b0), "r"(b1));
}
__device__ __forceinline__ __half2 u2h(uint32_t u) { return *(__half2*)&u; }

__global__ __launch_bounds__(TPB, CTAS_PER_SM)
void edge_mlp_f16_kernel(const int*   __restrict__ src,
                         const int*   __restrict__ dst,
                         const float* __restrict__ b2,
                         float*       __restrict__ out,
                         int E, int ntiles)
{
    extern __shared__ char smem[];
    const uint32_t smem_base = smem_u32(smem);
    float4* sEA = (float4*)(smem + SM_EA);
    float2* sEB = (float2*)(smem + SM_EB);
    float*  sB2 = (float*)(smem + SM_B2);

    const int tid   = threadIdx.x;
    const int wid   = tid >> 5;
    const int lane  = tid & 31;
    const int ngrid = gridDim.x;

    const uint32_t xw = smem_base + SM_X + (uint32_t)wid * SM_XW;

    // gather role constants
    const int el2   = lane >> 4;
    const int part  = (lane >> 3) & 1;
    const int chunk = lane & 7;

    // ---- stage-0 indices ----
    int tile0 = blockIdx.x;
    int ec = tile0 * TILE_M + wid * 32 + lane; if (ec >= E) ec = E - 1;
    int sv = src[ec], tv = dst[ec];

    // ---- B / epilogue-table staging (once) ----
    {
        const char* gB = (const char*)g_Bimg;
        uint32_t dB = smem_base + SM_B;
        #pragma unroll
        for (int i = 0; i < 9; ++i) {
            int c = i * TPB + tid;
            if (c < SM_B_SZ / 16) cp16(dB + (uint32_t)c * 16u, gB + c * 16);
        }
    }
    if (tid < 32) { sEA[tid] = g_EA[tid]; sEB[tid] = g_EB[tid]; }
    if (tid == 0) sB2[0] = b2[0];

    // ---- gather stage 0 ----
    #pragma unroll 8
    for (int i = 0; i < 16; ++i) {
        int ew = 2 * i + el2;
        int si = __shfl_sync(0xffffffffu, sv, ew);
        int ti = __shfl_sync(0xffffffffu, tv, ew);
        const __half* g = part ? g_hp_h + (size_t)ti * D + chunk * 8
                               : g_hc_h + (size_t)si * D + chunk * 8;
        cp16(xw + (uint32_t)ew * (XSTRH * 2u) + (uint32_t)(part * 128 + chunk * 16), g);
    }
    asm volatile("cp.async.commit_group;" ::: "memory");

    // ---- prefetch stage-1 indices ----
    {
        int bb = (tile0 + ngrid) * TILE_M + wid * 32 + lane;
        int ecl = (bb < E) ? bb : (E - 1);
        sv = src[ecl]; tv = dst[ecl];
    }

    asm volatile("cp.async.wait_group 0;" ::: "memory");
    __syncthreads();                 // B/tables visible; only CTA-wide barrier

    // ---- ldmatrix addresses ----
    const int j = lane >> 3;
    const int r = lane & 7;
    const uint32_t aA0 = xw + (uint32_t)(((j & 1) * 8 + r) * (XSTRH * 2)) + (uint32_t)(j >> 1) * 16u;
    const uint32_t aA1 = aA0 + 16u * (XSTRH * 2u);
    uint32_t aB[4];
    #pragma unroll
    for (int p = 0; p < 4; ++p)
        aB[p] = smem_base + SM_B
              + (uint32_t)((p * 16 + r + (j >> 1) * 8) * (BSTRH * 2))
              + (uint32_t)(j & 1) * 16u;

    const int qrow  = lane >> 2;
    const int qlane = lane & 3;
    const float bias2v = sB2[0];

    // =================== stage loop ===================
    for (int tile = tile0; tile < ntiles; tile += ngrid) {
        float acc[2][8][4];
        #pragma unroll
        for (int mt = 0; mt < 2; ++mt)
            #pragma unroll
            for (int nt = 0; nt < 8; ++nt)
                #pragma unroll
                for (int c = 0; c < 4; ++c) acc[mt][nt][c] = 0.f;

        __half2 cnh[2][2], cnt[2][2], cdp[2][2];
        #pragma unroll
        for (int mt = 0; mt < 2; ++mt)
            #pragma unroll
            for (int h = 0; h < 2; ++h) {
                cnh[mt][h] = __float2half2_rn(0.f);
                cnt[mt][h] = __float2half2_rn(0.f);
                cdp[mt][h] = __float2half2_rn(0.f);
            }

        // ---- fused k-loop: pairs (ks, ks+4) = (head cols, tail cols) ----
        #pragma unroll
        for (int ksp = 0; ksp < 4; ++ksp) {
            const uint32_t ko  = (uint32_t)ksp * 32u;
            const uint32_t ko2 = ko + 128u;

            uint32_t ah[2][4], at[2][4];
            ldsm_x4(ah[0][0], ah[0][1], ah[0][2], ah[0][3], aA0 + ko);
            ldsm_x4(ah[1][0], ah[1][1], ah[1][2], ah[1][3], aA1 + ko);
            ldsm_x4(at[0][0], at[0][1], at[0][2], at[0][3], aA0 + ko2);
            ldsm_x4(at[1][0], at[1][1], at[1][2], at[1][3], aA1 + ko2);

            // All 16 A-LDSMs of this stage are issued once ksp==3's are out:
            // issue next-stage gather here so its L2 latency hides under the
            // remaining MMAs + finalize + epilogue instead of epilogue only.
            if (ksp == 3) {
                if (tile + ngrid < ntiles) {
                    #pragma unroll 8
                    for (int i = 0; i < 16; ++i) {
                        int ew = 2 * i + el2;
                        int si = __shfl_sync(0xffffffffu, sv, ew);
                        int ti = __shfl_sync(0xffffffffu, tv, ew);
                        const __half* g = part ? g_hp_h + (size_t)ti * D + chunk * 8
                                               : g_hc_h + (size_t)si * D + chunk * 8;
                        cp16(xw + (uint32_t)ew * (XSTRH * 2u) + (uint32_t)(part * 128 + chunk * 16), g);
                    }
                }
                asm volatile("cp.async.commit_group;" ::: "memory");
                // prefetch indices for stage after next
                int bb = (tile + 2 * ngrid) * TILE_M + wid * 32 + lane;
                int ecl = (bb < E) ? bb : (E - 1);
                sv = src[ecl]; tv = dst[ecl];
            }

            // cosine partials from fragments
            #pragma unroll
            for (int mt = 0; mt < 2; ++mt) {
                __half2 h0a = u2h(ah[mt][0]), h0b = u2h(ah[mt][2]);
                __half2 h1a = u2h(ah[mt][1]), h1b = u2h(ah[mt][3]);
                __half2 t0a = u2h(at[mt][0]), t0b = u2h(at[mt][2]);
                __half2 t1a = u2h(at[mt][1]), t1b = u2h(at[mt][3]);
                cnh[mt][0] = __hfma2(h0a, h0a, cnh[mt][0]);
                cnh[mt][0] = __hfma2(h0b, h0b, cnh[mt][0]);
                cnh[mt][1] = __hfma2(h1a, h1a, cnh[mt][1]);
                cnh[mt][1] = __hfma2(h1b, h1b, cnh[mt][1]);
                cnt[mt][0] = __hfma2(t0a, t0a, cnt[mt][0]);
                cnt[mt][0] = __hfma2(t0b, t0b, cnt[mt][0]);
                cnt[mt][1] = __hfma2(t1a, t1a, cnt[mt][1]);
                cnt[mt][1] = __hfma2(t1b, t1b, cnt[mt][1]);
                cdp[mt][0] = __hfma2(h0a, t0a, cdp[mt][0]);
                cdp[mt][0] = __hfma2(h0b, t0b, cdp[mt][0]);
                cdp[mt][1] = __hfma2(h1a, t1a, cdp[mt][1]);
                cdp[mt][1] = __hfma2(h1b, t1b, cdp[mt][1]);
            }

            // B fragments + MMAs: head k-step
            {
                uint32_t bf[8][2];
                #pragma unroll
                for (int p = 0; p < 4; ++p) {
                    uint32_t r0, r1, r2, r3;
                    ldsm_x4(r0, r1, r2, r3, aB[p] + ko);
                    bf[2*p][0] = r0;   bf[2*p][1] = r1;
                    bf[2*p+1][0] = r2; bf[2*p+1][1] = r3;
                }
                #pragma unroll
                for (int nt = 0; nt < 8; ++nt) {
                    mma_f16(acc[0][nt], ah[0][0], ah[0][1], ah[0][2], ah[0][3], bf[nt][0], bf[nt][1]);
                    mma_f16(acc[1][nt], ah[1][0], ah[1][1], ah[1][2], ah[1][3], bf[nt][0], bf[nt][1]);
                }
            }
            // tail k-step
            {
                uint32_t bf[8][2];
                #pragma unroll
                for (int p = 0; p < 4; ++p) {
                    uint32_t r0, r1, r2, r3;
                    ldsm_x4(r0, r1, r2, r3, aB[p] + ko2);
                    bf[2*p][0] = r0;   bf[2*p][1] = r1;
                    bf[2*p+1][0] = r2; bf[2*p+1][1] = r3;
                }
                #pragma unroll
                for (int nt = 0; nt < 8; ++nt) {
                    mma_f16(acc[0][nt], at[0][0], at[0][1], at[0][2], at[0][3], bf[nt][0], bf[nt][1]);
                    mma_f16(acc[1][nt], at[1][0], at[1][1], at[1][2], at[1][3], bf[nt][0], bf[nt][1]);
                }
            }
        }

        // ---- finalize cosines (quad butterfly -> all lanes have row sums) ----
        float cos4[2][2];
        #pragma unroll
        for (int mt = 0; mt < 2; ++mt)
            #pragma unroll
            for (int h = 0; h < 2; ++h) {
                float2 a = __half22float2(cnh[mt][h]);
                float2 b = __half22float2(cnt[mt][h]);
                float2 c = __half22float2(cdp[mt][h]);
                float nh = a.x + a.y, nt = b.x + b.y, dp = c.x + c.y;
                nh += __shfl_xor_sync(0xffffffffu, nh, 1);
                nh += __shfl_xor_sync(0xffffffffu, nh, 2);
                nt += __shfl_xor_sync(0xffffffffu, nt, 1);
                nt += __shfl_xor_sync(0xffffffffu, nt, 2);
                dp += __shfl_xor_sync(0xffffffffu, dp, 1);
                dp += __shfl_xor_sync(0xffffffffu, dp, 2);
                cos4[mt][h] = dp * rsqrtf(fmaxf(nh * nt, 1e-24f));
            }

        // ---- epilogue: +cos*w1c + b1, relu, dot W2, sigmoid ----
        {
            float4 ea[8]; float2 eb[8];
            #pragma unroll
            for (int nt = 0; nt < 8; ++nt) {
                ea[nt] = sEA[nt * 4 + qlane];
                eb[nt] = sEB[nt * 4 + qlane];
            }
            const int ebase = tile * TILE_M + wid * 32;
            #pragma unroll
            for (int mt = 0; mt < 2; ++mt) {
                #pragma unroll
                for (int rr = 0; rr < 2; ++rr) {
                    const float cR = cos4[mt][rr];
                    float z = 0.f;
                    #pragma unroll
                    for (int nt = 0; nt < 8; ++nt) {
                        float v0 = acc[mt][nt][2*rr]     + fmaf(cR, ea[nt].x, ea[nt].z);
                        float v1 = acc[mt][nt][2*rr + 1] + fmaf(cR, ea[nt].y, ea[nt].w);
                        z = fmaf(fmaxf(v0, 0.f), eb[nt].x, z);
                        z = fmaf(fmaxf(v1, 0.f), eb[nt].y, z);
                    }
                    z += __shfl_xor_sync(0xffffffffu, z, 1);
                    z += __shfl_xor_sync(0xffffffffu, z, 2);
                    if (qlane == 0) {
                        int eo = ebase + mt * 16 + rr * 8 + qrow;
                        if (eo < E) {
                            float zz = z + bias2v;
                            float ez = __expf(-zz);
                            out[eo] = __fdividef(1.0f, 1.0f + ez);
                        }
                    }
                }
            }
        }

        asm volatile("cp.async.wait_group 0;" ::: "memory");
        __syncwarp();
    }
}

extern "C" void kernel_launch(void* const* d_in, const int* in_sizes, int n_in,
                              void* d_out, int out_size)
{
    const float* hc  = (const float*)d_in[0];
    const float* hp  = (const float*)d_in[1];
    const int*   src = (const int*)  d_in[2];
    const int*   dst = (const int*)  d_in[3];
    const float* W1  = (const float*)d_in[4];
    const float* b1  = (const float*)d_in[5];
    const float* W2  = (const float*)d_in[6];
    const float* b2  = (const float*)d_in[7];
    float* out = (float*)d_out;

    static int nsm = 0;
    if (!nsm) {
        cudaDeviceGetAttribute(&nsm, cudaDevAttrMultiProcessorCount, 0);
        cudaFuncSetAttribute(edge_mlp_f16_kernel,
                             cudaFuncAttributeMaxDynamicSharedMemorySize, SM_TOTAL);
    }

    int E   = in_sizes[2];
    int n4c = in_sizes[0] / 4;
    int n4p = in_sizes[1] / 4;
    int n4  = n4c + n4p;

    prep_all<<<(n4 + 255) / 256, 256>>>(hc, hp, W1, b1, W2, n4c, n4p);

    int ntiles = (E + TILE_M - 1) / TILE_M;
    int ngrid  = nsm * CTAS_PER_SM;
    if (ngrid > ntiles) ngrid = ntiles;
    edge_mlp_f16_kernel<<<ngrid, TPB, SM_TOTAL>>>(src, dst, b2, out, E, ntiles);
}